// round 10
// baseline (speedup 1.0000x reference)
#include <cuda_runtime.h>
#include <cuda_bf16.h>
#include <math.h>
#include <cstdint>

// ---------------- dimensions ----------------
#define DB 8
#define DM 1024
#define DD 768
#define DN 64
#define DP 16
#define DH 1536
#define DS 1024   // n*p

// ---------------- scratch ----------------
__device__ float g_phin[DN * DP * DD];
__device__ float g_logits[DB * DM * DS];
__device__ float g_D[DB * DM * DS];
__device__ float g_C[DB * DM * DS];
__device__ float g_Xs[DB * DS * DD];
__device__ float g_LN[DN * DB * DP * DD];       // [n][b*16+p][d]
__device__ float g_hdn[DN * (DB * DP) * DH];    // [n][128][h]
__device__ float g_Ys[DB * DS * DD];            // [b][s][d]

// ================= helpers =================
__device__ __forceinline__ uint32_t smem_to_u32(const void* p) {
    uint32_t a;
    asm("{ .reg .u64 t; cvta.to.shared.u64 t, %1; cvt.u32.u64 %0, t; }" : "=r"(a) : "l"(p));
    return a;
}

// fast split: hi = truncate-to-bf16 (bit mask), lo = rn(x - hi)
__device__ __forceinline__ void split4(float4 v, uint32_t& h01, uint32_t& h23,
                                       uint32_t& l01, uint32_t& l23) {
    uint32_t ux = __float_as_uint(v.x), uy = __float_as_uint(v.y);
    uint32_t uz = __float_as_uint(v.z), uw = __float_as_uint(v.w);
    h01 = __byte_perm(ux, uy, 0x7632);
    h23 = __byte_perm(uz, uw, 0x7632);
    float hx = __uint_as_float(ux & 0xFFFF0000u);
    float hy = __uint_as_float(uy & 0xFFFF0000u);
    float hz = __uint_as_float(uz & 0xFFFF0000u);
    float hw = __uint_as_float(uw & 0xFFFF0000u);
    asm("cvt.rn.bf16x2.f32 %0, %1, %2;" : "=r"(l01) : "f"(v.y - hy), "f"(v.x - hx));
    asm("cvt.rn.bf16x2.f32 %0, %1, %2;" : "=r"(l23) : "f"(v.w - hw), "f"(v.z - hz));
}

__device__ __forceinline__ void ldsm_x4(uint32_t* r, uint32_t addr) {
    asm volatile("ldmatrix.sync.aligned.m8n8.x4.shared.b16 {%0,%1,%2,%3}, [%4];"
                 : "=r"(r[0]), "=r"(r[1]), "=r"(r[2]), "=r"(r[3]) : "r"(addr));
}
__device__ __forceinline__ void ldsm_x4_t(uint32_t* r, uint32_t addr) {
    asm volatile("ldmatrix.sync.aligned.m8n8.x4.trans.shared.b16 {%0,%1,%2,%3}, [%4];"
                 : "=r"(r[0]), "=r"(r[1]), "=r"(r[2]), "=r"(r[3]) : "r"(addr));
}
__device__ __forceinline__ void mma_bf16(float* d, const uint32_t* a, const uint32_t* b) {
    asm volatile(
        "mma.sync.aligned.m16n8k16.row.col.f32.bf16.bf16.f32 "
        "{%0,%1,%2,%3}, {%4,%5,%6,%7}, {%8,%9}, {%0,%1,%2,%3};"
        : "+f"(d[0]), "+f"(d[1]), "+f"(d[2]), "+f"(d[3])
        : "r"(a[0]), "r"(a[1]), "r"(a[2]), "r"(a[3]), "r"(b[0]), "r"(b[1]));
}

// ================= elementwise kernels =================
__global__ void phi_norm_kernel(const float* __restrict__ phi, float* __restrict__ phin) {
    int i = blockIdx.x * blockDim.x + threadIdx.x;
    if (i >= DP * DD) return;
    float s = 0.f;
#pragma unroll 4
    for (int n = 0; n < DN; n++) { float v = phi[n * (DP * DD) + i]; s += v * v; }
    float r = rsqrtf(s + 1e-6f);
#pragma unroll 4
    for (int n = 0; n < DN; n++) phin[n * (DP * DD) + i] = phi[n * (DP * DD) + i] * r;
}

__global__ void softmax_row_kernel(const float* __restrict__ L, float* __restrict__ O) {
    const float* Lr = L + (size_t)blockIdx.x * DS;
    float* Or = O + (size_t)blockIdx.x * DS;
    int t = threadIdx.x;
    float v[4]; float mx = -1e30f;
#pragma unroll
    for (int j = 0; j < 4; j++) { v[j] = Lr[t + j * 256]; mx = fmaxf(mx, v[j]); }
    __shared__ float sd[256];
    sd[t] = mx; __syncthreads();
    for (int off = 128; off > 0; off >>= 1) { if (t < off) sd[t] = fmaxf(sd[t], sd[t + off]); __syncthreads(); }
    mx = sd[0]; __syncthreads();
    float sum = 0.f;
#pragma unroll
    for (int j = 0; j < 4; j++) { v[j] = expf(v[j] - mx); sum += v[j]; }
    sd[t] = sum; __syncthreads();
    for (int off = 128; off > 0; off >>= 1) { if (t < off) sd[t] += sd[t + off]; __syncthreads(); }
    float inv = 1.f / sd[0];
#pragma unroll
    for (int j = 0; j < 4; j++) Or[t + j * 256] = v[j] * inv;
}

// 512 threads: (32, 16)
__global__ void softmax_col_kernel(const float* __restrict__ L, float* __restrict__ O) {
    int b = blockIdx.y;
    int s = blockIdx.x * 32 + threadIdx.x;
    int ty = threadIdx.y;   // 0..15
    const float* Lb = L + (size_t)b * DM * DS;
    float* Ob = O + (size_t)b * DM * DS;
    __shared__ float red[16][32];
    float mx = -1e30f;
    for (int m = ty; m < DM; m += 16) mx = fmaxf(mx, Lb[(size_t)m * DS + s]);
    red[ty][threadIdx.x] = mx; __syncthreads();
    if (ty == 0) {
        float v = red[0][threadIdx.x];
#pragma unroll
        for (int i = 1; i < 16; i++) v = fmaxf(v, red[i][threadIdx.x]);
        red[0][threadIdx.x] = v;
    }
    __syncthreads();
    mx = red[0][threadIdx.x]; __syncthreads();
    float sum = 0.f;
    for (int m = ty; m < DM; m += 16) sum += expf(Lb[(size_t)m * DS + s] - mx);
    red[ty][threadIdx.x] = sum; __syncthreads();
    if (ty == 0) {
        float v = 0.f;
#pragma unroll
        for (int i = 0; i < 16; i++) v += red[i][threadIdx.x];
        red[0][threadIdx.x] = v;
    }
    __syncthreads();
    float inv = 1.f / red[0][threadIdx.x];
    for (int m = ty; m < DM; m += 16)
        Ob[(size_t)m * DS + s] = expf(Lb[(size_t)m * DS + s] - mx) * inv;
}

// LayerNorm: read Xs [b][n*16+p][d], write LN [n][b*16+p][d]
__global__ void layernorm_kernel(const float* __restrict__ X, float* __restrict__ Yo,
                                 const float* __restrict__ g, const float* __restrict__ bb) {
    int row = blockIdx.x;
    int b = row >> 10;
    int slot = row & 1023;
    int n = slot >> 4;
    int p = slot & 15;
    const float* Xr = X + (size_t)row * DD;
    float* Yr = Yo + ((size_t)n * 128 + b * 16 + p) * DD;
    __shared__ float sh[DD];
    __shared__ float red[256];
    int t = threadIdx.x;
    float ls = 0.f;
    for (int j = t; j < DD; j += 256) { float v = Xr[j]; sh[j] = v; ls += v; }
    red[t] = ls; __syncthreads();
    for (int off = 128; off > 0; off >>= 1) { if (t < off) red[t] += red[t + off]; __syncthreads(); }
    float mu = red[0] * (1.0f / DD); __syncthreads();
    float lv = 0.f;
    for (int j = t; j < DD; j += 256) { float dv = sh[j] - mu; lv += dv * dv; }
    red[t] = lv; __syncthreads();
    for (int off = 128; off > 0; off >>= 1) { if (t < off) red[t] += red[t + off]; __syncthreads(); }
    float is = rsqrtf(red[0] * (1.0f / DD) + 1e-5f); __syncthreads();
    for (int j = t; j < DD; j += 256)
        Yr[j] = (sh[j] - mu) * is * g[n * DD + j] + bb[n * DD + j];
}

// ================= mma.sync GEMM =================
// 256 threads, 8 warps in 4(M)x2(N); warp tile 32x32; CTA tile 128x64, kc=32.
// bf16 3-term split, 2-stage smem, DOUBLE reg buffer -> LDG->STS distance 2 iters.
// TA/TB: 0 = row-major [row][K], 1 = K-major [K][row]
// EPI: 0 none, 1 +bias, 2 +bias+gelu ; CSC: 1 = scattered output rows
template <int TA, int TB, int EPI, int CSC>
__global__ void __launch_bounds__(256, 2)
gemm_mma(const float* __restrict__ A, const float* __restrict__ B,
         float* __restrict__ C, const float* __restrict__ bias,
         int K, int lda, int ldb, int ldc,
         long long aBS, long long bBS, long long cBS, int biasBS, long long c_sb) {
    constexpr int ASZ1 = TA ? 32 * 272 : 128 * 80;   // one plane of A tile (128 x kc)
    constexpr int BSZ1 = TB ? 32 * 144 : 64 * 80;    // one plane of B tile (64 x kc)
    constexpr int STAGE = 2 * ASZ1 + 2 * BSZ1;
    extern __shared__ char smem[];
    const uint32_t sm0 = smem_to_u32(smem);

    const int tid = threadIdx.x;
    const int l = tid & 31;
    const int wid = tid >> 5;       // 0..7
    const int wm = wid & 3;         // 4 M groups of 32 rows
    const int wn = wid >> 2;        // 2 N groups of 32 cols
    const int z = blockIdx.z;
    const int bm = blockIdx.y * 128;
    const int bn = blockIdx.x * 64;
    const int NC = K >> 5;

    const float* Ab = A + (size_t)z * aBS + (TA ? (size_t)bm : (size_t)bm * lda);
    const float* Bb = B + (size_t)z * bBS + (TB ? (size_t)bn : (size_t)bn * ldb);

    float4 ra[2][4], rb[2][2];   // double-buffered LDG registers

    auto LDG = [&](int c, int bi) {
        int k0 = c * 32;
#pragma unroll
        for (int i = 0; i < 4; i++) {
            int p = tid + i * 256;   // 1024 float4 of A
            if (TA) ra[bi][i] = *(const float4*)(Ab + (size_t)(k0 + (p >> 5)) * lda + (p & 31) * 4);
            else    ra[bi][i] = *(const float4*)(Ab + (size_t)(p >> 3) * lda + k0 + (p & 7) * 4);
        }
#pragma unroll
        for (int i = 0; i < 2; i++) {
            int p = tid + i * 256;   // 512 float4 of B
            if (TB) rb[bi][i] = *(const float4*)(Bb + (size_t)(k0 + (p >> 4)) * ldb + (p & 15) * 4);
            else    rb[bi][i] = *(const float4*)(Bb + (size_t)(p >> 3) * ldb + k0 + (p & 7) * 4);
        }
    };

    auto STS = [&](int s, int bi) {
        char* st = smem + s * STAGE;
        char* ahis = st;
        char* alos = st + ASZ1;
        char* bhis = st + 2 * ASZ1;
        char* blos = st + 2 * ASZ1 + BSZ1;
#pragma unroll
        for (int i = 0; i < 4; i++) {
            int p = tid + i * 256;
            int aoff = TA ? ((p >> 5) * 272 + (p & 31) * 8) : ((p >> 3) * 80 + (p & 7) * 8);
            uint32_t h01, h23, l01, l23;
            split4(ra[bi][i], h01, h23, l01, l23);
            *(uint2*)(ahis + aoff) = make_uint2(h01, h23);
            *(uint2*)(alos + aoff) = make_uint2(l01, l23);
        }
#pragma unroll
        for (int i = 0; i < 2; i++) {
            int p = tid + i * 256;
            int boff = TB ? ((p >> 4) * 144 + (p & 15) * 8) : ((p >> 3) * 80 + (p & 7) * 8);
            uint32_t h01, h23, l01, l23;
            split4(rb[bi][i], h01, h23, l01, l23);
            *(uint2*)(bhis + boff) = make_uint2(h01, h23);
            *(uint2*)(blos + boff) = make_uint2(l01, l23);
        }
    };

    float acc[2][4][4];
#pragma unroll
    for (int mt = 0; mt < 2; mt++)
#pragma unroll
        for (int nt = 0; nt < 4; nt++)
#pragma unroll
            for (int q = 0; q < 4; q++) acc[mt][nt][q] = 0.f;

    auto COMPUTE = [&](int s) {
        uint32_t sbA = sm0 + s * STAGE;
        uint32_t sbB = sbA + 2 * ASZ1;
#pragma unroll
        for (int ks = 0; ks < 2; ks++) {
            uint32_t ahi[2][4], alo[2][4];
#pragma unroll
            for (int mt = 0; mt < 2; mt++) {
                int mr = wm * 32 + mt * 16;
                if (TA) {
                    int krow = ks * 16 + (l & 7) + ((l >> 4) << 3);
                    int col = mr + (((l >> 3) & 1) << 3);
                    uint32_t addr = sbA + krow * 272 + col * 2;
                    ldsm_x4_t(ahi[mt], addr);
                    ldsm_x4_t(alo[mt], addr + ASZ1);
                } else {
                    int row = mr + (l & 15);
                    uint32_t addr = sbA + row * 80 + ks * 32 + ((l >> 4) & 1) * 16;
                    ldsm_x4(ahi[mt], addr);
                    ldsm_x4(alo[mt], addr + ASZ1);
                }
            }
#pragma unroll
            for (int np = 0; np < 2; np++) {
                int nr = wn * 32 + np * 16;
                uint32_t bhi[4], blo[4];
                if (TB) {
                    int krow = ks * 16 + (l & 7) + (((l >> 3) & 1) << 3);
                    int col = nr + ((l >> 4) << 3);
                    uint32_t addr = sbB + krow * 144 + col * 2;
                    ldsm_x4_t(bhi, addr);
                    ldsm_x4_t(blo, addr + BSZ1);
                } else {
                    int row = nr + (l & 7) + ((l >> 4) << 3);
                    uint32_t addr = sbB + row * 80 + ks * 32 + (((l >> 3) & 1) << 4);
                    ldsm_x4(bhi, addr);
                    ldsm_x4(blo, addr + BSZ1);
                }
#pragma unroll
                for (int half = 0; half < 2; half++) {
                    int nt = np * 2 + half;
#pragma unroll
                    for (int mt = 0; mt < 2; mt++) {
                        mma_bf16(acc[mt][nt], ahi[mt], bhi + 2 * half);
                        mma_bf16(acc[mt][nt], alo[mt], bhi + 2 * half);
                        mma_bf16(acc[mt][nt], ahi[mt], blo + 2 * half);
                    }
                }
            }
        }
    };

    // prologue: chunk0 -> stage0; chunk1 -> buf1; chunk2 -> buf0 (buf0 freed by STS(0))
    LDG(0, 0);
    STS(0, 0);
    if (NC > 1) LDG(1, 1);
    if (NC > 2) LDG(2, 0);
    __syncthreads();
    // iter c: STS(c+1) from buf[(c+1)&1]; refill that buf with chunk c+3; compute c.
    for (int c = 0; c < NC; c++) {
        int bi = (c + 1) & 1;
        if (c + 1 < NC) STS((c + 1) & 1, bi);
        if (c + 3 < NC) LDG(c + 3, bi);
        COMPUTE(c & 1);
        __syncthreads();
    }

    // ---------------- epilogue via smem staging ----------------
    float* Cs = (float*)smem;   // [128][68]
#pragma unroll
    for (int mt = 0; mt < 2; mt++) {
#pragma unroll
        for (int nt = 0; nt < 4; nt++) {
            int r0 = wm * 32 + mt * 16 + (l >> 2);
            int c0 = wn * 32 + nt * 8 + (l & 3) * 2;
            Cs[r0 * 68 + c0] = acc[mt][nt][0];
            Cs[r0 * 68 + c0 + 1] = acc[mt][nt][1];
            Cs[(r0 + 8) * 68 + c0] = acc[mt][nt][2];
            Cs[(r0 + 8) * 68 + c0 + 1] = acc[mt][nt][3];
        }
    }
    __syncthreads();
    const float* bp = (EPI >= 1) ? (bias + (size_t)z * biasBS + bn) : nullptr;
#pragma unroll 4
    for (int i = 0; i < 32; i++) {
        int idx = i * 256 + tid;       // 8192 elements
        int r = idx >> 6, cc = idx & 63;
        float v = Cs[r * 68 + cc];
        if (EPI >= 1) v += __ldg(bp + cc);
        if (EPI == 2) v = 0.5f * v * (1.0f + erff(v * 0.70710678118654752440f));
        size_t off;
        if (CSC)
            off = (size_t)z * cBS + (size_t)(r >> 4) * c_sb + (size_t)(r & 15) * ldc + bn + cc;
        else
            off = (size_t)z * cBS + (size_t)(bm + r) * ldc + bn + cc;
        C[off] = v;
    }
}

// ================= host launcher =================
extern "C" void kernel_launch(void* const* d_in, const int* in_sizes, int n_in,
                              void* d_out, int out_size) {
    const float* x    = (const float*)d_in[0];
    const float* phi  = (const float*)d_in[1];
    const float* ln_g = (const float*)d_in[2];
    const float* ln_b = (const float*)d_in[3];
    const float* w1   = (const float*)d_in[4];
    const float* b1   = (const float*)d_in[5];
    const float* w2   = (const float*)d_in[6];
    const float* b2   = (const float*)d_in[7];
    float* out = (float*)d_out;

    float *phin, *logits, *Dbuf, *Cbuf, *Xs, *LN, *hdn, *Ys;
    cudaGetSymbolAddress((void**)&phin, g_phin);
    cudaGetSymbolAddress((void**)&logits, g_logits);
    cudaGetSymbolAddress((void**)&Dbuf, g_D);
    cudaGetSymbolAddress((void**)&Cbuf, g_C);
    cudaGetSymbolAddress((void**)&Xs, g_Xs);
    cudaGetSymbolAddress((void**)&LN, g_LN);
    cudaGetSymbolAddress((void**)&hdn, g_hdn);
    cudaGetSymbolAddress((void**)&Ys, g_Ys);

    // smem: max(2 pipeline stages, epilogue staging 128*68*4 = 34816)
    const int EPI_BYTES = 128 * 68 * 4;
    auto mx = [](int a, int b) { return a > b ? a : b; };
    const int SM00 = mx(2 * (2 * 128 * 80 + 2 * 64 * 80), EPI_BYTES);    // 61440
    const int SM11 = mx(2 * (2 * 32 * 272 + 2 * 32 * 144), EPI_BYTES);   // 53248
    const int SM01 = mx(2 * (2 * 128 * 80 + 2 * 32 * 144), EPI_BYTES);   // 59392
    cudaFuncSetAttribute(gemm_mma<0,0,0,0>, cudaFuncAttributeMaxDynamicSharedMemorySize, SM00);
    cudaFuncSetAttribute(gemm_mma<1,1,0,0>, cudaFuncAttributeMaxDynamicSharedMemorySize, SM11);
    cudaFuncSetAttribute(gemm_mma<0,1,2,0>, cudaFuncAttributeMaxDynamicSharedMemorySize, SM01);
    cudaFuncSetAttribute(gemm_mma<0,1,1,1>, cudaFuncAttributeMaxDynamicSharedMemorySize, SM01);
    cudaFuncSetAttribute(gemm_mma<0,1,0,0>, cudaFuncAttributeMaxDynamicSharedMemorySize, SM01);

    // 1. normalize phi
    phi_norm_kernel<<<(DP * DD + 255) / 256, 256>>>(phi, phin);

    // 2. logits[8192,1024] = x @ phin^T    (grid 16x64 = 1024 CTAs)
    gemm_mma<0,0,0,0><<<dim3(DS / 64, (DB * DM) / 128, 1), 256, SM00>>>(
        x, phin, logits, nullptr, DD, DD, DD, DS, 0, 0, 0, 0, 0);

    // 3a. dispatch softmax (D) — needed by gemm4
    softmax_col_kernel<<<dim3(DS / 32, DB), dim3(32, 16)>>>(logits, Dbuf);

    // 4. Xs[b][s][d] = D_b^T @ x_b    (launch index 3 -> ncu-profiled slot)
    gemm_mma<1,1,0,0><<<dim3(DD / 64, DS / 128, DB), 256, SM11>>>(
        Dbuf, x, Xs, nullptr, DM, DS, DD, DD,
        (long long)DM * DS, (long long)DM * DD, (long long)DS * DD, 0, 0);

    // 3b. combine softmax (C) — only needed by gemm8, so it can run here
    softmax_row_kernel<<<DB * DM, 256>>>(logits, Cbuf);

    // 5. LayerNorm + gather into expert layout
    layernorm_kernel<<<DB * DS, 256>>>(Xs, LN, ln_g, ln_b);

    // 6. hdn[n][128][h] = LN[n] @ w1[n] + b1, GELU   (grid 24x1x64 = 1536 CTAs)
    gemm_mma<0,1,2,0><<<dim3(DH / 64, 1, DN), 256, SM01>>>(
        LN, w1, hdn, b1, DD, DD, DH, DH,
        (long long)128 * DD, (long long)DD * DH, (long long)128 * DH, DH, 0);

    // 7. Ys[b][n*16+p][d] = hdn[n] @ w2[n] + b2  (scattered C; 12x1x64 = 768 CTAs)
    gemm_mma<0,1,1,1><<<dim3(DD / 64, 1, DN), 256, SM01>>>(
        hdn, w2, Ys, b2, DH, DH, DD, DD,
        (long long)128 * DH, (long long)DH * DD, (long long)DP * DD, DD,
        (long long)DS * DD);

    // 8. Y[b][m][d] = C_b @ Ys_b   (grid 12x8x8 = 768 CTAs)
    gemm_mma<0,1,0,0><<<dim3(DD / 64, DM / 128, DB), 256, SM01>>>(
        Cbuf, Ys, out, nullptr, DS, DS, DD, DD,
        (long long)DM * DS, (long long)DS * DD, (long long)DM * DD, 0, 0);
}

// round 11
// speedup vs baseline: 1.5437x; 1.5437x over previous
#include <cuda_runtime.h>
#include <cuda_bf16.h>
#include <math.h>
#include <cstdint>

// ---------------- dimensions ----------------
#define DB 8
#define DM 1024
#define DD 768
#define DN 64
#define DP 16
#define DH 1536
#define DS 1024   // n*p

// ---------------- scratch ----------------
__device__ float g_phin[DN * DP * DD];
__device__ float g_logits[DB * DM * DS];
__device__ float g_D[DB * DM * DS];
__device__ float g_C[DB * DM * DS];
__device__ float g_Xs[DB * DS * DD];
__device__ float g_LN[DN * DB * DP * DD];       // [n][b*16+p][d]
__device__ float g_hdn[DN * (DB * DP) * DH];    // [n][128][h]
__device__ float g_Ys[DB * DS * DD];            // [b][s][d]

// ================= helpers =================
__device__ __forceinline__ uint32_t smem_to_u32(const void* p) {
    uint32_t a;
    asm("{ .reg .u64 t; cvta.to.shared.u64 t, %1; cvt.u32.u64 %0, t; }" : "=r"(a) : "l"(p));
    return a;
}

// fast split: hi = truncate-to-bf16 (bit mask), lo = rn(x - hi)
__device__ __forceinline__ void split4(float4 v, uint32_t& h01, uint32_t& h23,
                                       uint32_t& l01, uint32_t& l23) {
    uint32_t ux = __float_as_uint(v.x), uy = __float_as_uint(v.y);
    uint32_t uz = __float_as_uint(v.z), uw = __float_as_uint(v.w);
    h01 = __byte_perm(ux, uy, 0x7632);
    h23 = __byte_perm(uz, uw, 0x7632);
    float hx = __uint_as_float(ux & 0xFFFF0000u);
    float hy = __uint_as_float(uy & 0xFFFF0000u);
    float hz = __uint_as_float(uz & 0xFFFF0000u);
    float hw = __uint_as_float(uw & 0xFFFF0000u);
    asm("cvt.rn.bf16x2.f32 %0, %1, %2;" : "=r"(l01) : "f"(v.y - hy), "f"(v.x - hx));
    asm("cvt.rn.bf16x2.f32 %0, %1, %2;" : "=r"(l23) : "f"(v.w - hw), "f"(v.z - hz));
}

__device__ __forceinline__ void ldsm_x4(uint32_t* r, uint32_t addr) {
    asm volatile("ldmatrix.sync.aligned.m8n8.x4.shared.b16 {%0,%1,%2,%3}, [%4];"
                 : "=r"(r[0]), "=r"(r[1]), "=r"(r[2]), "=r"(r[3]) : "r"(addr));
}
__device__ __forceinline__ void ldsm_x4_t(uint32_t* r, uint32_t addr) {
    asm volatile("ldmatrix.sync.aligned.m8n8.x4.trans.shared.b16 {%0,%1,%2,%3}, [%4];"
                 : "=r"(r[0]), "=r"(r[1]), "=r"(r[2]), "=r"(r[3]) : "r"(addr));
}
__device__ __forceinline__ void mma_bf16(float* d, const uint32_t* a, const uint32_t* b) {
    asm volatile(
        "mma.sync.aligned.m16n8k16.row.col.f32.bf16.bf16.f32 "
        "{%0,%1,%2,%3}, {%4,%5,%6,%7}, {%8,%9}, {%0,%1,%2,%3};"
        : "+f"(d[0]), "+f"(d[1]), "+f"(d[2]), "+f"(d[3])
        : "r"(a[0]), "r"(a[1]), "r"(a[2]), "r"(a[3]), "r"(b[0]), "r"(b[1]));
}

// ================= elementwise kernels =================
__global__ void phi_norm_kernel(const float* __restrict__ phi, float* __restrict__ phin) {
    int i = blockIdx.x * blockDim.x + threadIdx.x;
    if (i >= DP * DD) return;
    float s = 0.f;
#pragma unroll 4
    for (int n = 0; n < DN; n++) { float v = phi[n * (DP * DD) + i]; s += v * v; }
    float r = rsqrtf(s + 1e-6f);
#pragma unroll 4
    for (int n = 0; n < DN; n++) phin[n * (DP * DD) + i] = phi[n * (DP * DD) + i] * r;
}

__global__ void softmax_row_kernel(const float* __restrict__ L, float* __restrict__ O) {
    const float* Lr = L + (size_t)blockIdx.x * DS;
    float* Or = O + (size_t)blockIdx.x * DS;
    int t = threadIdx.x;
    float v[4]; float mx = -1e30f;
#pragma unroll
    for (int j = 0; j < 4; j++) { v[j] = Lr[t + j * 256]; mx = fmaxf(mx, v[j]); }
    __shared__ float sd[256];
    sd[t] = mx; __syncthreads();
    for (int off = 128; off > 0; off >>= 1) { if (t < off) sd[t] = fmaxf(sd[t], sd[t + off]); __syncthreads(); }
    mx = sd[0]; __syncthreads();
    float sum = 0.f;
#pragma unroll
    for (int j = 0; j < 4; j++) { v[j] = expf(v[j] - mx); sum += v[j]; }
    sd[t] = sum; __syncthreads();
    for (int off = 128; off > 0; off >>= 1) { if (t < off) sd[t] += sd[t + off]; __syncthreads(); }
    float inv = 1.f / sd[0];
#pragma unroll
    for (int j = 0; j < 4; j++) Or[t + j * 256] = v[j] * inv;
}

// 512 threads: (32, 16)
__global__ void softmax_col_kernel(const float* __restrict__ L, float* __restrict__ O) {
    int b = blockIdx.y;
    int s = blockIdx.x * 32 + threadIdx.x;
    int ty = threadIdx.y;   // 0..15
    const float* Lb = L + (size_t)b * DM * DS;
    float* Ob = O + (size_t)b * DM * DS;
    __shared__ float red[16][32];
    float mx = -1e30f;
    for (int m = ty; m < DM; m += 16) mx = fmaxf(mx, Lb[(size_t)m * DS + s]);
    red[ty][threadIdx.x] = mx; __syncthreads();
    if (ty == 0) {
        float v = red[0][threadIdx.x];
#pragma unroll
        for (int i = 1; i < 16; i++) v = fmaxf(v, red[i][threadIdx.x]);
        red[0][threadIdx.x] = v;
    }
    __syncthreads();
    mx = red[0][threadIdx.x]; __syncthreads();
    float sum = 0.f;
    for (int m = ty; m < DM; m += 16) sum += expf(Lb[(size_t)m * DS + s] - mx);
    red[ty][threadIdx.x] = sum; __syncthreads();
    if (ty == 0) {
        float v = 0.f;
#pragma unroll
        for (int i = 0; i < 16; i++) v += red[i][threadIdx.x];
        red[0][threadIdx.x] = v;
    }
    __syncthreads();
    float inv = 1.f / red[0][threadIdx.x];
    for (int m = ty; m < DM; m += 16)
        Ob[(size_t)m * DS + s] = expf(Lb[(size_t)m * DS + s] - mx) * inv;
}

// LayerNorm: read Xs [b][n*16+p][d], write LN [n][b*16+p][d]
__global__ void layernorm_kernel(const float* __restrict__ X, float* __restrict__ Yo,
                                 const float* __restrict__ g, const float* __restrict__ bb) {
    int row = blockIdx.x;
    int b = row >> 10;
    int slot = row & 1023;
    int n = slot >> 4;
    int p = slot & 15;
    const float* Xr = X + (size_t)row * DD;
    float* Yr = Yo + ((size_t)n * 128 + b * 16 + p) * DD;
    __shared__ float sh[DD];
    __shared__ float red[256];
    int t = threadIdx.x;
    float ls = 0.f;
    for (int j = t; j < DD; j += 256) { float v = Xr[j]; sh[j] = v; ls += v; }
    red[t] = ls; __syncthreads();
    for (int off = 128; off > 0; off >>= 1) { if (t < off) red[t] += red[t + off]; __syncthreads(); }
    float mu = red[0] * (1.0f / DD); __syncthreads();
    float lv = 0.f;
    for (int j = t; j < DD; j += 256) { float dv = sh[j] - mu; lv += dv * dv; }
    red[t] = lv; __syncthreads();
    for (int off = 128; off > 0; off >>= 1) { if (t < off) red[t] += red[t + off]; __syncthreads(); }
    float is = rsqrtf(red[0] * (1.0f / DD) + 1e-5f); __syncthreads();
    for (int j = t; j < DD; j += 256)
        Yr[j] = (sh[j] - mu) * is * g[n * DD + j] + bb[n * DD + j];
}

// ================= mma.sync GEMM =================
// 256 threads, 8 warps in 4(M)x2(N); warp tile 32x32; CTA tile 128x64, kc=32.
// bf16 3-term split, 2-stage smem, distance-2 LDG->STS via STATIC double reg
// buffers (unroll-by-2 mainloop; all register arrays statically indexed).
// TA/TB: 0 = row-major [row][K], 1 = K-major [K][row]
// EPI: 0 none, 1 +bias, 2 +bias+gelu ; CSC: 1 = scattered output rows
template <int TA, int TB, int EPI, int CSC>
__global__ void __launch_bounds__(256, 2)
gemm_mma(const float* __restrict__ A, const float* __restrict__ B,
         float* __restrict__ C, const float* __restrict__ bias,
         int K, int lda, int ldb, int ldc,
         long long aBS, long long bBS, long long cBS, int biasBS, long long c_sb) {
    constexpr int ASZ1 = TA ? 32 * 272 : 128 * 80;   // one plane of A tile (128 x kc)
    constexpr int BSZ1 = TB ? 32 * 144 : 64 * 80;    // one plane of B tile (64 x kc)
    constexpr int STAGE = 2 * ASZ1 + 2 * BSZ1;
    extern __shared__ char smem[];
    const uint32_t sm0 = smem_to_u32(smem);

    const int tid = threadIdx.x;
    const int l = tid & 31;
    const int wid = tid >> 5;       // 0..7
    const int wm = wid & 3;         // 4 M groups of 32 rows
    const int wn = wid >> 2;        // 2 N groups of 32 cols
    const int z = blockIdx.z;
    const int bm = blockIdx.y * 128;
    const int bn = blockIdx.x * 64;
    const int NC = K >> 5;          // even for all our K (24/32/48)

    const float* Ab = A + (size_t)z * aBS + (TA ? (size_t)bm : (size_t)bm * lda);
    const float* Bb = B + (size_t)z * bBS + (TB ? (size_t)bn : (size_t)bn * ldb);

    float4 ra0[4], rb0[2], ra1[4], rb1[2];   // two statically-named LDG buffers

    auto LDGb = [&](int c, float4* raX, float4* rbX) {
        int k0 = c * 32;
#pragma unroll
        for (int i = 0; i < 4; i++) {
            int p = tid + i * 256;   // 1024 float4 of A
            if (TA) raX[i] = *(const float4*)(Ab + (size_t)(k0 + (p >> 5)) * lda + (p & 31) * 4);
            else    raX[i] = *(const float4*)(Ab + (size_t)(p >> 3) * lda + k0 + (p & 7) * 4);
        }
#pragma unroll
        for (int i = 0; i < 2; i++) {
            int p = tid + i * 256;   // 512 float4 of B
            if (TB) rbX[i] = *(const float4*)(Bb + (size_t)(k0 + (p >> 4)) * ldb + (p & 15) * 4);
            else    rbX[i] = *(const float4*)(Bb + (size_t)(p >> 3) * ldb + k0 + (p & 7) * 4);
        }
    };

    auto STSb = [&](int s, const float4* raX, const float4* rbX) {
        char* st = smem + s * STAGE;
        char* ahis = st;
        char* alos = st + ASZ1;
        char* bhis = st + 2 * ASZ1;
        char* blos = st + 2 * ASZ1 + BSZ1;
#pragma unroll
        for (int i = 0; i < 4; i++) {
            int p = tid + i * 256;
            int aoff = TA ? ((p >> 5) * 272 + (p & 31) * 8) : ((p >> 3) * 80 + (p & 7) * 8);
            uint32_t h01, h23, l01, l23;
            split4(raX[i], h01, h23, l01, l23);
            *(uint2*)(ahis + aoff) = make_uint2(h01, h23);
            *(uint2*)(alos + aoff) = make_uint2(l01, l23);
        }
#pragma unroll
        for (int i = 0; i < 2; i++) {
            int p = tid + i * 256;
            int boff = TB ? ((p >> 4) * 144 + (p & 15) * 8) : ((p >> 3) * 80 + (p & 7) * 8);
            uint32_t h01, h23, l01, l23;
            split4(rbX[i], h01, h23, l01, l23);
            *(uint2*)(bhis + boff) = make_uint2(h01, h23);
            *(uint2*)(blos + boff) = make_uint2(l01, l23);
        }
    };

    float acc[2][4][4];
#pragma unroll
    for (int mt = 0; mt < 2; mt++)
#pragma unroll
        for (int nt = 0; nt < 4; nt++)
#pragma unroll
            for (int q = 0; q < 4; q++) acc[mt][nt][q] = 0.f;

    auto COMPUTE = [&](int s) {
        uint32_t sbA = sm0 + s * STAGE;
        uint32_t sbB = sbA + 2 * ASZ1;
#pragma unroll
        for (int ks = 0; ks < 2; ks++) {
            uint32_t ahi[2][4], alo[2][4];
#pragma unroll
            for (int mt = 0; mt < 2; mt++) {
                int mr = wm * 32 + mt * 16;
                if (TA) {
                    int krow = ks * 16 + (l & 7) + ((l >> 4) << 3);
                    int col = mr + (((l >> 3) & 1) << 3);
                    uint32_t addr = sbA + krow * 272 + col * 2;
                    ldsm_x4_t(ahi[mt], addr);
                    ldsm_x4_t(alo[mt], addr + ASZ1);
                } else {
                    int row = mr + (l & 15);
                    uint32_t addr = sbA + row * 80 + ks * 32 + ((l >> 4) & 1) * 16;
                    ldsm_x4(ahi[mt], addr);
                    ldsm_x4(alo[mt], addr + ASZ1);
                }
            }
#pragma unroll
            for (int np = 0; np < 2; np++) {
                int nr = wn * 32 + np * 16;
                uint32_t bhi[4], blo[4];
                if (TB) {
                    int krow = ks * 16 + (l & 7) + (((l >> 3) & 1) << 3);
                    int col = nr + ((l >> 4) << 3);
                    uint32_t addr = sbB + krow * 144 + col * 2;
                    ldsm_x4_t(bhi, addr);
                    ldsm_x4_t(blo, addr + BSZ1);
                } else {
                    int row = nr + (l & 7) + ((l >> 4) << 3);
                    uint32_t addr = sbB + row * 80 + ks * 32 + (((l >> 3) & 1) << 4);
                    ldsm_x4(bhi, addr);
                    ldsm_x4(blo, addr + BSZ1);
                }
#pragma unroll
                for (int half = 0; half < 2; half++) {
                    int nt = np * 2 + half;
#pragma unroll
                    for (int mt = 0; mt < 2; mt++) {
                        mma_bf16(acc[mt][nt], ahi[mt], bhi + 2 * half);
                        mma_bf16(acc[mt][nt], alo[mt], bhi + 2 * half);
                        mma_bf16(acc[mt][nt], ahi[mt], blo + 2 * half);
                    }
                }
            }
        }
    };

    // prologue: chunk0 -> buf0 -> stage0; chunk1 -> buf1; chunk2 -> buf0.
    // chunk k lives in buf[k&1]; stage k&1 holds chunk k while computing.
    LDGb(0, ra0, rb0);
    STSb(0, ra0, rb0);
    if (NC > 1) LDGb(1, ra1, rb1);
    if (NC > 2) LDGb(2, ra0, rb0);
    __syncthreads();
    for (int c = 0; c < NC; c += 2) {
        // even iter: STS chunk c+1 (buf1) to stage1; prefetch chunk c+3 into buf1.
        if (c + 1 < NC) STSb(1, ra1, rb1);
        if (c + 3 < NC) LDGb(c + 3, ra1, rb1);
        COMPUTE(0);
        __syncthreads();
        // odd iter: STS chunk c+2 (buf0) to stage0; prefetch chunk c+4 into buf0.
        if (c + 2 < NC) STSb(0, ra0, rb0);
        if (c + 4 < NC) LDGb(c + 4, ra0, rb0);
        if (c + 1 < NC) COMPUTE(1);
        __syncthreads();
    }

    // ---------------- epilogue via smem staging ----------------
    float* Cs = (float*)smem;   // [128][68]
#pragma unroll
    for (int mt = 0; mt < 2; mt++) {
#pragma unroll
        for (int nt = 0; nt < 4; nt++) {
            int r0 = wm * 32 + mt * 16 + (l >> 2);
            int c0 = wn * 32 + nt * 8 + (l & 3) * 2;
            Cs[r0 * 68 + c0] = acc[mt][nt][0];
            Cs[r0 * 68 + c0 + 1] = acc[mt][nt][1];
            Cs[(r0 + 8) * 68 + c0] = acc[mt][nt][2];
            Cs[(r0 + 8) * 68 + c0 + 1] = acc[mt][nt][3];
        }
    }
    __syncthreads();
    const float* bp = (EPI >= 1) ? (bias + (size_t)z * biasBS + bn) : nullptr;
#pragma unroll 4
    for (int i = 0; i < 32; i++) {
        int idx = i * 256 + tid;       // 8192 elements
        int r = idx >> 6, cc = idx & 63;
        float v = Cs[r * 68 + cc];
        if (EPI >= 1) v += __ldg(bp + cc);
        if (EPI == 2) v = 0.5f * v * (1.0f + erff(v * 0.70710678118654752440f));
        size_t off;
        if (CSC)
            off = (size_t)z * cBS + (size_t)(r >> 4) * c_sb + (size_t)(r & 15) * ldc + bn + cc;
        else
            off = (size_t)z * cBS + (size_t)(bm + r) * ldc + bn + cc;
        C[off] = v;
    }
}

// ================= host launcher =================
extern "C" void kernel_launch(void* const* d_in, const int* in_sizes, int n_in,
                              void* d_out, int out_size) {
    const float* x    = (const float*)d_in[0];
    const float* phi  = (const float*)d_in[1];
    const float* ln_g = (const float*)d_in[2];
    const float* ln_b = (const float*)d_in[3];
    const float* w1   = (const float*)d_in[4];
    const float* b1   = (const float*)d_in[5];
    const float* w2   = (const float*)d_in[6];
    const float* b2   = (const float*)d_in[7];
    float* out = (float*)d_out;

    float *phin, *logits, *Dbuf, *Cbuf, *Xs, *LN, *hdn, *Ys;
    cudaGetSymbolAddress((void**)&phin, g_phin);
    cudaGetSymbolAddress((void**)&logits, g_logits);
    cudaGetSymbolAddress((void**)&Dbuf, g_D);
    cudaGetSymbolAddress((void**)&Cbuf, g_C);
    cudaGetSymbolAddress((void**)&Xs, g_Xs);
    cudaGetSymbolAddress((void**)&LN, g_LN);
    cudaGetSymbolAddress((void**)&hdn, g_hdn);
    cudaGetSymbolAddress((void**)&Ys, g_Ys);

    // smem: max(2 pipeline stages, epilogue staging 128*68*4 = 34816)
    const int EPI_BYTES = 128 * 68 * 4;
    auto mx = [](int a, int b) { return a > b ? a : b; };
    const int SM00 = mx(2 * (2 * 128 * 80 + 2 * 64 * 80), EPI_BYTES);    // 61440
    const int SM11 = mx(2 * (2 * 32 * 272 + 2 * 32 * 144), EPI_BYTES);   // 53248
    const int SM01 = mx(2 * (2 * 128 * 80 + 2 * 32 * 144), EPI_BYTES);   // 59392
    cudaFuncSetAttribute(gemm_mma<0,0,0,0>, cudaFuncAttributeMaxDynamicSharedMemorySize, SM00);
    cudaFuncSetAttribute(gemm_mma<1,1,0,0>, cudaFuncAttributeMaxDynamicSharedMemorySize, SM11);
    cudaFuncSetAttribute(gemm_mma<0,1,2,0>, cudaFuncAttributeMaxDynamicSharedMemorySize, SM01);
    cudaFuncSetAttribute(gemm_mma<0,1,1,1>, cudaFuncAttributeMaxDynamicSharedMemorySize, SM01);
    cudaFuncSetAttribute(gemm_mma<0,1,0,0>, cudaFuncAttributeMaxDynamicSharedMemorySize, SM01);

    // 1. normalize phi
    phi_norm_kernel<<<(DP * DD + 255) / 256, 256>>>(phi, phin);

    // 2. logits[8192,1024] = x @ phin^T    (grid 16x64 = 1024 CTAs)
    gemm_mma<0,0,0,0><<<dim3(DS / 64, (DB * DM) / 128, 1), 256, SM00>>>(
        x, phin, logits, nullptr, DD, DD, DD, DS, 0, 0, 0, 0, 0);

    // 3a. dispatch softmax (D) — needed by gemm4
    softmax_col_kernel<<<dim3(DS / 32, DB), dim3(32, 16)>>>(logits, Dbuf);

    // 4. Xs[b][s][d] = D_b^T @ x_b    (launch index 3 -> ncu-profiled slot)
    gemm_mma<1,1,0,0><<<dim3(DD / 64, DS / 128, DB), 256, SM11>>>(
        Dbuf, x, Xs, nullptr, DM, DS, DD, DD,
        (long long)DM * DS, (long long)DM * DD, (long long)DS * DD, 0, 0);

    // 3b. combine softmax (C) — only needed by gemm8
    softmax_row_kernel<<<DB * DM, 256>>>(logits, Cbuf);

    // 5. LayerNorm + gather into expert layout
    layernorm_kernel<<<DB * DS, 256>>>(Xs, LN, ln_g, ln_b);

    // 6. hdn[n][128][h] = LN[n] @ w1[n] + b1, GELU   (grid 24x1x64 = 1536 CTAs)
    gemm_mma<0,1,2,0><<<dim3(DH / 64, 1, DN), 256, SM01>>>(
        LN, w1, hdn, b1, DD, DD, DH, DH,
        (long long)128 * DD, (long long)DD * DH, (long long)128 * DH, DH, 0);

    // 7. Ys[b][n*16+p][d] = hdn[n] @ w2[n] + b2  (scattered C; 12x1x64 = 768 CTAs)
    gemm_mma<0,1,1,1><<<dim3(DD / 64, 1, DN), 256, SM01>>>(
        hdn, w2, Ys, b2, DH, DH, DD, DD,
        (long long)128 * DH, (long long)DH * DD, (long long)DP * DD, DD,
        (long long)DS * DD);

    // 8. Y[b][m][d] = C_b @ Ys_b   (grid 12x8x8 = 768 CTAs)
    gemm_mma<0,1,0,0><<<dim3(DD / 64, DM / 128, DB), 256, SM01>>>(
        Cbuf, Ys, out, nullptr, DS, DS, DD, DD,
        (long long)DM * DS, (long long)DS * DD, (long long)DM * DD, 0, 0);
}

// round 12
// speedup vs baseline: 1.5916x; 1.0311x over previous
#include <cuda_runtime.h>
#include <cuda_bf16.h>
#include <cuda_fp16.h>
#include <math.h>
#include <cstdint>

// ---------------- dimensions ----------------
#define DB 8
#define DM 1024
#define DD 768
#define DN 64
#define DP 16
#define DH 1536
#define DS 1024   // n*p

// ---------------- scratch ----------------
__device__ float g_phin[DN * DP * DD];
__device__ float g_logits[DB * DM * DS];
__device__ float g_D[DB * DM * DS];
__device__ float g_C[DB * DM * DS];
__device__ float g_Xs[DB * DS * DD];
__device__ float g_LN[DN * DB * DP * DD];       // [n][b*16+p][d]
__device__ float g_hdn[DN * (DB * DP) * DH];    // [n][128][h]
__device__ float g_Ys[DB * DS * DD];            // [b][s][d]

// ================= helpers =================
__device__ __forceinline__ uint32_t smem_to_u32(const void* p) {
    uint32_t a;
    asm("{ .reg .u64 t; cvta.to.shared.u64 t, %1; cvt.u32.u64 %0, t; }" : "=r"(a) : "l"(p));
    return a;
}

// fp16 2-level split: hi = rn(x), lo = rn(x - hi)
__device__ __forceinline__ void split4h(float4 v, uint32_t& h01, uint32_t& h23,
                                        uint32_t& l01, uint32_t& l23) {
    asm("cvt.rn.f16x2.f32 %0, %1, %2;" : "=r"(h01) : "f"(v.y), "f"(v.x));
    asm("cvt.rn.f16x2.f32 %0, %1, %2;" : "=r"(h23) : "f"(v.w), "f"(v.z));
    float2 f01 = __half22float2(*reinterpret_cast<__half2*>(&h01));
    float2 f23 = __half22float2(*reinterpret_cast<__half2*>(&h23));
    asm("cvt.rn.f16x2.f32 %0, %1, %2;" : "=r"(l01) : "f"(v.y - f01.y), "f"(v.x - f01.x));
    asm("cvt.rn.f16x2.f32 %0, %1, %2;" : "=r"(l23) : "f"(v.w - f23.y), "f"(v.z - f23.x));
}

// fp16 single rounding
__device__ __forceinline__ void hi4h(float4 v, uint32_t& h01, uint32_t& h23) {
    asm("cvt.rn.f16x2.f32 %0, %1, %2;" : "=r"(h01) : "f"(v.y), "f"(v.x));
    asm("cvt.rn.f16x2.f32 %0, %1, %2;" : "=r"(h23) : "f"(v.w), "f"(v.z));
}

__device__ __forceinline__ void ldsm_x4(uint32_t* r, uint32_t addr) {
    asm volatile("ldmatrix.sync.aligned.m8n8.x4.shared.b16 {%0,%1,%2,%3}, [%4];"
                 : "=r"(r[0]), "=r"(r[1]), "=r"(r[2]), "=r"(r[3]) : "r"(addr));
}
__device__ __forceinline__ void ldsm_x4_t(uint32_t* r, uint32_t addr) {
    asm volatile("ldmatrix.sync.aligned.m8n8.x4.trans.shared.b16 {%0,%1,%2,%3}, [%4];"
                 : "=r"(r[0]), "=r"(r[1]), "=r"(r[2]), "=r"(r[3]) : "r"(addr));
}
__device__ __forceinline__ void mma_f16(float* d, const uint32_t* a, const uint32_t* b) {
    asm volatile(
        "mma.sync.aligned.m16n8k16.row.col.f32.f16.f16.f32 "
        "{%0,%1,%2,%3}, {%4,%5,%6,%7}, {%8,%9}, {%0,%1,%2,%3};"
        : "+f"(d[0]), "+f"(d[1]), "+f"(d[2]), "+f"(d[3])
        : "r"(a[0]), "r"(a[1]), "r"(a[2]), "r"(a[3]), "r"(b[0]), "r"(b[1]));
}

// ================= elementwise kernels =================
__global__ void phi_norm_kernel(const float* __restrict__ phi, float* __restrict__ phin) {
    int i = blockIdx.x * blockDim.x + threadIdx.x;
    if (i >= DP * DD) return;
    float s = 0.f;
#pragma unroll 4
    for (int n = 0; n < DN; n++) { float v = phi[n * (DP * DD) + i]; s += v * v; }
    float r = rsqrtf(s + 1e-6f);
#pragma unroll 4
    for (int n = 0; n < DN; n++) phin[n * (DP * DD) + i] = phi[n * (DP * DD) + i] * r;
}

__global__ void softmax_row_kernel(const float* __restrict__ L, float* __restrict__ O) {
    const float* Lr = L + (size_t)blockIdx.x * DS;
    float* Or = O + (size_t)blockIdx.x * DS;
    int t = threadIdx.x;
    float v[4]; float mx = -1e30f;
#pragma unroll
    for (int j = 0; j < 4; j++) { v[j] = Lr[t + j * 256]; mx = fmaxf(mx, v[j]); }
    __shared__ float sd[256];
    sd[t] = mx; __syncthreads();
    for (int off = 128; off > 0; off >>= 1) { if (t < off) sd[t] = fmaxf(sd[t], sd[t + off]); __syncthreads(); }
    mx = sd[0]; __syncthreads();
    float sum = 0.f;
#pragma unroll
    for (int j = 0; j < 4; j++) { v[j] = expf(v[j] - mx); sum += v[j]; }
    sd[t] = sum; __syncthreads();
    for (int off = 128; off > 0; off >>= 1) { if (t < off) sd[t] += sd[t + off]; __syncthreads(); }
    float inv = 1.f / sd[0];
#pragma unroll
    for (int j = 0; j < 4; j++) Or[t + j * 256] = v[j] * inv;
}

// 512 threads: (32, 16)
__global__ void softmax_col_kernel(const float* __restrict__ L, float* __restrict__ O) {
    int b = blockIdx.y;
    int s = blockIdx.x * 32 + threadIdx.x;
    int ty = threadIdx.y;   // 0..15
    const float* Lb = L + (size_t)b * DM * DS;
    float* Ob = O + (size_t)b * DM * DS;
    __shared__ float red[16][32];
    float mx = -1e30f;
    for (int m = ty; m < DM; m += 16) mx = fmaxf(mx, Lb[(size_t)m * DS + s]);
    red[ty][threadIdx.x] = mx; __syncthreads();
    if (ty == 0) {
        float v = red[0][threadIdx.x];
#pragma unroll
        for (int i = 1; i < 16; i++) v = fmaxf(v, red[i][threadIdx.x]);
        red[0][threadIdx.x] = v;
    }
    __syncthreads();
    mx = red[0][threadIdx.x]; __syncthreads();
    float sum = 0.f;
    for (int m = ty; m < DM; m += 16) sum += expf(Lb[(size_t)m * DS + s] - mx);
    red[ty][threadIdx.x] = sum; __syncthreads();
    if (ty == 0) {
        float v = 0.f;
#pragma unroll
        for (int i = 0; i < 16; i++) v += red[i][threadIdx.x];
        red[0][threadIdx.x] = v;
    }
    __syncthreads();
    float inv = 1.f / red[0][threadIdx.x];
    for (int m = ty; m < DM; m += 16)
        Ob[(size_t)m * DS + s] = expf(Lb[(size_t)m * DS + s] - mx) * inv;
}

// LayerNorm: read Xs [b][n*16+p][d], write LN [n][b*16+p][d]
__global__ void layernorm_kernel(const float* __restrict__ X, float* __restrict__ Yo,
                                 const float* __restrict__ g, const float* __restrict__ bb) {
    int row = blockIdx.x;
    int b = row >> 10;
    int slot = row & 1023;
    int n = slot >> 4;
    int p = slot & 15;
    const float* Xr = X + (size_t)row * DD;
    float* Yr = Yo + ((size_t)n * 128 + b * 16 + p) * DD;
    __shared__ float sh[DD];
    __shared__ float red[256];
    int t = threadIdx.x;
    float ls = 0.f;
    for (int j = t; j < DD; j += 256) { float v = Xr[j]; sh[j] = v; ls += v; }
    red[t] = ls; __syncthreads();
    for (int off = 128; off > 0; off >>= 1) { if (t < off) red[t] += red[t + off]; __syncthreads(); }
    float mu = red[0] * (1.0f / DD); __syncthreads();
    float lv = 0.f;
    for (int j = t; j < DD; j += 256) { float dv = sh[j] - mu; lv += dv * dv; }
    red[t] = lv; __syncthreads();
    for (int off = 128; off > 0; off >>= 1) { if (t < off) red[t] += red[t + off]; __syncthreads(); }
    float is = rsqrtf(red[0] * (1.0f / DD) + 1e-5f); __syncthreads();
    for (int j = t; j < DD; j += 256)
        Yr[j] = (sh[j] - mu) * is * g[n * DD + j] + bb[n * DD + j];
}

// ================= mma.sync GEMM =================
// 256 threads, 8 warps 4(M)x2(N); warp tile 32x32; CTA tile 128x64, kc=32.
// fp16 split; MODE 0 = 3-term (A hi+lo, B hi+lo — near-exact), MODE 1 = 2-term
// (A hi+lo, B single-rounded). R9 schedule: one sync/iter, distance-1 prefetch.
// MINB = min blocks/SM for launch_bounds (occupancy driver).
// TA/TB: 0 = row-major [row][K], 1 = K-major [K][row]
// EPI: 0 none, 1 +bias, 2 +bias+gelu ; CSC: 1 = scattered output rows
template <int TA, int TB, int EPI, int CSC, int MODE, int MINB>
__global__ void __launch_bounds__(256, MINB)
gemm_mma(const float* __restrict__ A, const float* __restrict__ B,
         float* __restrict__ C, const float* __restrict__ bias,
         int K, int lda, int ldb, int ldc,
         long long aBS, long long bBS, long long cBS, int biasBS, long long c_sb) {
    constexpr int ASZ1 = TA ? 32 * 272 : 128 * 80;   // one plane of A tile (128 x kc)
    constexpr int BSZ1 = TB ? 32 * 144 : 64 * 80;    // one plane of B tile (64 x kc)
    constexpr int BPL = (MODE == 0) ? 2 : 1;         // B planes
    constexpr int STAGE = 2 * ASZ1 + BPL * BSZ1;
    extern __shared__ char smem[];
    const uint32_t sm0 = smem_to_u32(smem);

    const int tid = threadIdx.x;
    const int l = tid & 31;
    const int wid = tid >> 5;       // 0..7
    const int wm = wid & 3;         // 4 M groups of 32 rows
    const int wn = wid >> 2;        // 2 N groups of 32 cols
    const int z = blockIdx.z;
    const int bm = blockIdx.y * 128;
    const int bn = blockIdx.x * 64;
    const int NC = K >> 5;

    const float* Ab = A + (size_t)z * aBS + (TA ? (size_t)bm : (size_t)bm * lda);
    const float* Bb = B + (size_t)z * bBS + (TB ? (size_t)bn : (size_t)bn * ldb);

    float4 ra[4], rb[2];

    auto LDG = [&](int c) {
        int k0 = c * 32;
#pragma unroll
        for (int i = 0; i < 4; i++) {
            int p = tid + i * 256;   // 1024 float4 of A
            if (TA) ra[i] = *(const float4*)(Ab + (size_t)(k0 + (p >> 5)) * lda + (p & 31) * 4);
            else    ra[i] = *(const float4*)(Ab + (size_t)(p >> 3) * lda + k0 + (p & 7) * 4);
        }
#pragma unroll
        for (int i = 0; i < 2; i++) {
            int p = tid + i * 256;   // 512 float4 of B
            if (TB) rb[i] = *(const float4*)(Bb + (size_t)(k0 + (p >> 4)) * ldb + (p & 15) * 4);
            else    rb[i] = *(const float4*)(Bb + (size_t)(p >> 3) * ldb + k0 + (p & 7) * 4);
        }
    };

    auto STS = [&](int s) {
        char* st = smem + s * STAGE;
        char* ahis = st;
        char* alos = st + ASZ1;
        char* bhis = st + 2 * ASZ1;
        char* blos = st + 2 * ASZ1 + BSZ1;   // only valid when MODE==0
#pragma unroll
        for (int i = 0; i < 4; i++) {
            int p = tid + i * 256;
            int aoff = TA ? ((p >> 5) * 272 + (p & 31) * 8) : ((p >> 3) * 80 + (p & 7) * 8);
            uint32_t h01, h23, l01, l23;
            split4h(ra[i], h01, h23, l01, l23);
            *(uint2*)(ahis + aoff) = make_uint2(h01, h23);
            *(uint2*)(alos + aoff) = make_uint2(l01, l23);
        }
#pragma unroll
        for (int i = 0; i < 2; i++) {
            int p = tid + i * 256;
            int boff = TB ? ((p >> 4) * 144 + (p & 15) * 8) : ((p >> 3) * 80 + (p & 7) * 8);
            if (MODE == 0) {
                uint32_t h01, h23, l01, l23;
                split4h(rb[i], h01, h23, l01, l23);
                *(uint2*)(bhis + boff) = make_uint2(h01, h23);
                *(uint2*)(blos + boff) = make_uint2(l01, l23);
            } else {
                uint32_t h01, h23;
                hi4h(rb[i], h01, h23);
                *(uint2*)(bhis + boff) = make_uint2(h01, h23);
            }
        }
    };

    float acc[2][4][4];
#pragma unroll
    for (int mt = 0; mt < 2; mt++)
#pragma unroll
        for (int nt = 0; nt < 4; nt++)
#pragma unroll
            for (int q = 0; q < 4; q++) acc[mt][nt][q] = 0.f;

    auto COMPUTE = [&](int s) {
        uint32_t sbA = sm0 + s * STAGE;
        uint32_t sbB = sbA + 2 * ASZ1;
#pragma unroll
        for (int ks = 0; ks < 2; ks++) {
            uint32_t ahi[2][4], alo[2][4];
#pragma unroll
            for (int mt = 0; mt < 2; mt++) {
                int mr = wm * 32 + mt * 16;
                if (TA) {
                    int krow = ks * 16 + (l & 7) + ((l >> 4) << 3);
                    int col = mr + (((l >> 3) & 1) << 3);
                    uint32_t addr = sbA + krow * 272 + col * 2;
                    ldsm_x4_t(ahi[mt], addr);
                    ldsm_x4_t(alo[mt], addr + ASZ1);
                } else {
                    int row = mr + (l & 15);
                    uint32_t addr = sbA + row * 80 + ks * 32 + ((l >> 4) & 1) * 16;
                    ldsm_x4(ahi[mt], addr);
                    ldsm_x4(alo[mt], addr + ASZ1);
                }
            }
#pragma unroll
            for (int np = 0; np < 2; np++) {
                int nr = wn * 32 + np * 16;
                uint32_t bhi[4], blo[4];
                if (TB) {
                    int krow = ks * 16 + (l & 7) + (((l >> 3) & 1) << 3);
                    int col = nr + ((l >> 4) << 3);
                    uint32_t addr = sbB + krow * 144 + col * 2;
                    ldsm_x4_t(bhi, addr);
                    if (MODE == 0) ldsm_x4_t(blo, addr + BSZ1);
                } else {
                    int row = nr + (l & 7) + ((l >> 4) << 3);
                    uint32_t addr = sbB + row * 80 + ks * 32 + (((l >> 3) & 1) << 4);
                    ldsm_x4(bhi, addr);
                    if (MODE == 0) ldsm_x4(blo, addr + BSZ1);
                }
#pragma unroll
                for (int half = 0; half < 2; half++) {
                    int nt = np * 2 + half;
#pragma unroll
                    for (int mt = 0; mt < 2; mt++) {
                        mma_f16(acc[mt][nt], ahi[mt], bhi + 2 * half);
                        mma_f16(acc[mt][nt], alo[mt], bhi + 2 * half);
                        if (MODE == 0) mma_f16(acc[mt][nt], ahi[mt], blo + 2 * half);
                    }
                }
            }
        }
    };

    LDG(0);
    STS(0);
    if (NC > 1) LDG(1);
    __syncthreads();
    for (int c = 0; c < NC; c++) {
        if (c + 1 < NC) STS((c + 1) & 1);
        if (c + 2 < NC) LDG(c + 2);
        COMPUTE(c & 1);
        __syncthreads();
    }

    // ---------------- epilogue via smem staging ----------------
    float* Cs = (float*)smem;   // [128][68]
#pragma unroll
    for (int mt = 0; mt < 2; mt++) {
#pragma unroll
        for (int nt = 0; nt < 4; nt++) {
            int r0 = wm * 32 + mt * 16 + (l >> 2);
            int c0 = wn * 32 + nt * 8 + (l & 3) * 2;
            Cs[r0 * 68 + c0] = acc[mt][nt][0];
            Cs[r0 * 68 + c0 + 1] = acc[mt][nt][1];
            Cs[(r0 + 8) * 68 + c0] = acc[mt][nt][2];
            Cs[(r0 + 8) * 68 + c0 + 1] = acc[mt][nt][3];
        }
    }
    __syncthreads();
    const float* bp = (EPI >= 1) ? (bias + (size_t)z * biasBS + bn) : nullptr;
#pragma unroll 4
    for (int i = 0; i < 32; i++) {
        int idx = i * 256 + tid;       // 8192 elements
        int r = idx >> 6, cc = idx & 63;
        float v = Cs[r * 68 + cc];
        if (EPI >= 1) v += __ldg(bp + cc);
        if (EPI == 2) v = 0.5f * v * (1.0f + erff(v * 0.70710678118654752440f));
        size_t off;
        if (CSC)
            off = (size_t)z * cBS + (size_t)(r >> 4) * c_sb + (size_t)(r & 15) * ldc + bn + cc;
        else
            off = (size_t)z * cBS + (size_t)(bm + r) * ldc + bn + cc;
        C[off] = v;
    }
}

// ================= host launcher =================
extern "C" void kernel_launch(void* const* d_in, const int* in_sizes, int n_in,
                              void* d_out, int out_size) {
    const float* x    = (const float*)d_in[0];
    const float* phi  = (const float*)d_in[1];
    const float* ln_g = (const float*)d_in[2];
    const float* ln_b = (const float*)d_in[3];
    const float* w1   = (const float*)d_in[4];
    const float* b1   = (const float*)d_in[5];
    const float* w2   = (const float*)d_in[6];
    const float* b2   = (const float*)d_in[7];
    float* out = (float*)d_out;

    float *phin, *logits, *Dbuf, *Cbuf, *Xs, *LN, *hdn, *Ys;
    cudaGetSymbolAddress((void**)&phin, g_phin);
    cudaGetSymbolAddress((void**)&logits, g_logits);
    cudaGetSymbolAddress((void**)&Dbuf, g_D);
    cudaGetSymbolAddress((void**)&Cbuf, g_C);
    cudaGetSymbolAddress((void**)&Xs, g_Xs);
    cudaGetSymbolAddress((void**)&LN, g_LN);
    cudaGetSymbolAddress((void**)&hdn, g_hdn);
    cudaGetSymbolAddress((void**)&Ys, g_Ys);

    // smem per CTA: max(2 pipeline stages, epilogue staging 128*68*4 = 34816)
    const int EPI_BYTES = 128 * 68 * 4;
    auto mx = [](int a, int b) { return a > b ? a : b; };
    const int SM_G2  = mx(2 * (2 * 128 * 80 + 2 * 64 * 80), EPI_BYTES);   // 61440 (MODE0)
    const int SM_G4  = mx(2 * (2 * 32 * 272 + 32 * 144), EPI_BYTES);      // 44032 (MODE1)
    const int SM_G67 = mx(2 * (2 * 128 * 80 + 32 * 144), EPI_BYTES);      // 50176 (MODE1)
    cudaFuncSetAttribute(gemm_mma<0,0,0,0,0,2>, cudaFuncAttributeMaxDynamicSharedMemorySize, SM_G2);
    cudaFuncSetAttribute(gemm_mma<1,1,0,0,1,3>, cudaFuncAttributeMaxDynamicSharedMemorySize, SM_G4);
    cudaFuncSetAttribute(gemm_mma<0,1,2,0,1,3>, cudaFuncAttributeMaxDynamicSharedMemorySize, SM_G67);
    cudaFuncSetAttribute(gemm_mma<0,1,1,1,1,3>, cudaFuncAttributeMaxDynamicSharedMemorySize, SM_G67);
    cudaFuncSetAttribute(gemm_mma<0,1,0,0,1,3>, cudaFuncAttributeMaxDynamicSharedMemorySize, SM_G67);

    // 1. normalize phi
    phi_norm_kernel<<<(DP * DD + 255) / 256, 256>>>(phi, phin);

    // 2. logits[8192,1024] = x @ phin^T   (MODE0: fp16 3-term, near-exact)
    gemm_mma<0,0,0,0,0,2><<<dim3(DS / 64, (DB * DM) / 128, 1), 256, SM_G2>>>(
        x, phin, logits, nullptr, DD, DD, DD, DS, 0, 0, 0, 0, 0);

    // 3a. dispatch softmax (D) — needed by gemm4
    softmax_col_kernel<<<dim3(DS / 32, DB), dim3(32, 16)>>>(logits, Dbuf);

    // 4. Xs[b][s][d] = D_b^T @ x_b    (launch index 3 -> ncu-profiled slot)
    gemm_mma<1,1,0,0,1,3><<<dim3(DD / 64, DS / 128, DB), 256, SM_G4>>>(
        Dbuf, x, Xs, nullptr, DM, DS, DD, DD,
        (long long)DM * DS, (long long)DM * DD, (long long)DS * DD, 0, 0);

    // 3b. combine softmax (C) — only needed by gemm8
    softmax_row_kernel<<<DB * DM, 256>>>(logits, Cbuf);

    // 5. LayerNorm + gather into expert layout
    layernorm_kernel<<<DB * DS, 256>>>(Xs, LN, ln_g, ln_b);

    // 6. hdn[n][128][h] = LN[n] @ w1[n] + b1, GELU   (1536 CTAs)
    gemm_mma<0,1,2,0,1,3><<<dim3(DH / 64, 1, DN), 256, SM_G67>>>(
        LN, w1, hdn, b1, DD, DD, DH, DH,
        (long long)128 * DD, (long long)DD * DH, (long long)128 * DH, DH, 0);

    // 7. Ys[b][n*16+p][d] = hdn[n] @ w2[n] + b2  (scattered C; 768 CTAs)
    gemm_mma<0,1,1,1,1,3><<<dim3(DD / 64, 1, DN), 256, SM_G67>>>(
        hdn, w2, Ys, b2, DH, DH, DD, DD,
        (long long)128 * DH, (long long)DH * DD, (long long)DP * DD, DD,
        (long long)DS * DD);

    // 8. Y[b][m][d] = C_b @ Ys_b   (768 CTAs)
    gemm_mma<0,1,0,0,1,3><<<dim3(DD / 64, DM / 128, DB), 256, SM_G67>>>(
        Cbuf, Ys, out, nullptr, DS, DS, DD, DD,
        (long long)DM * DS, (long long)DS * DD, (long long)DM * DD, 0, 0);
}

// round 13
// speedup vs baseline: 1.8738x; 1.1772x over previous
#include <cuda_runtime.h>
#include <cuda_fp16.h>
#include <math.h>
#include <cstdint>

// ---------------- dimensions ----------------
#define DB 8
#define DM 1024
#define DD 768
#define DN 64
#define DP 16
#define DH 1536
#define DS 1024   // n*p

typedef unsigned short u16;

// ---------------- scratch ----------------
__device__ float g_logits[DB * DM * DS];
__device__ float g_Xs[DB * DS * DD];
// fp16 hi/lo planes
__device__ u16 g_xh[DB * DM * DD], g_xl[DB * DM * DD];
__device__ u16 g_ph[DN * DP * DD], g_pl[DN * DP * DD];
__device__ u16 g_Ch[DB * DM * DS], g_Cl[DB * DM * DS];
__device__ u16 g_Dh[DB * DM * DS], g_Dl[DB * DM * DS];
__device__ u16 g_LNh[DN * DB * DP * DD], g_LNl[DN * DB * DP * DD];
__device__ u16 g_hh[DN * 128 * DH], g_hl[DN * 128 * DH];
__device__ u16 g_Yh[DB * DS * DD];

// ================= helpers =================
__device__ __forceinline__ uint32_t smem_to_u32(const void* p) {
    uint32_t a;
    asm("{ .reg .u64 t; cvta.to.shared.u64 t, %1; cvt.u32.u64 %0, t; }" : "=r"(a) : "l"(p));
    return a;
}

// fp16 2-level split helpers
__device__ __forceinline__ void split4h(float4 v, uint32_t& h01, uint32_t& h23,
                                        uint32_t& l01, uint32_t& l23) {
    asm("cvt.rn.f16x2.f32 %0, %1, %2;" : "=r"(h01) : "f"(v.y), "f"(v.x));
    asm("cvt.rn.f16x2.f32 %0, %1, %2;" : "=r"(h23) : "f"(v.w), "f"(v.z));
    float2 f01 = __half22float2(*reinterpret_cast<__half2*>(&h01));
    float2 f23 = __half22float2(*reinterpret_cast<__half2*>(&h23));
    asm("cvt.rn.f16x2.f32 %0, %1, %2;" : "=r"(l01) : "f"(v.y - f01.y), "f"(v.x - f01.x));
    asm("cvt.rn.f16x2.f32 %0, %1, %2;" : "=r"(l23) : "f"(v.w - f23.y), "f"(v.z - f23.x));
}
__device__ __forceinline__ void hi4h(float4 v, uint32_t& h01, uint32_t& h23) {
    asm("cvt.rn.f16x2.f32 %0, %1, %2;" : "=r"(h01) : "f"(v.y), "f"(v.x));
    asm("cvt.rn.f16x2.f32 %0, %1, %2;" : "=r"(h23) : "f"(v.w), "f"(v.z));
}
__device__ __forceinline__ void split1h(float v, u16& h, u16& lo) {
    u16 hh;
    asm("cvt.rn.f16.f32 %0, %1;" : "=h"(hh) : "f"(v));
    float hf = __half2float(*reinterpret_cast<__half*>(&hh));
    asm("cvt.rn.f16.f32 %0, %1;" : "=h"(lo) : "f"(v - hf));
    h = hh;
}

#define CP16(sm, g) \
    asm volatile("cp.async.cg.shared.global [%0], [%1], 16;" :: "r"(sm), "l"(g) : "memory")
#define CP_COMMIT() asm volatile("cp.async.commit_group;" ::: "memory")
#define CP_WAIT1()  asm volatile("cp.async.wait_group 1;" ::: "memory")

__device__ __forceinline__ void ldsm_x4(uint32_t* r, uint32_t addr) {
    asm volatile("ldmatrix.sync.aligned.m8n8.x4.shared.b16 {%0,%1,%2,%3}, [%4];"
                 : "=r"(r[0]), "=r"(r[1]), "=r"(r[2]), "=r"(r[3]) : "r"(addr));
}
__device__ __forceinline__ void ldsm_x4_t(uint32_t* r, uint32_t addr) {
    asm volatile("ldmatrix.sync.aligned.m8n8.x4.trans.shared.b16 {%0,%1,%2,%3}, [%4];"
                 : "=r"(r[0]), "=r"(r[1]), "=r"(r[2]), "=r"(r[3]) : "r"(addr));
}
__device__ __forceinline__ void mma_f16(float* d, const uint32_t* a, const uint32_t* b) {
    asm volatile(
        "mma.sync.aligned.m16n8k16.row.col.f32.f16.f16.f32 "
        "{%0,%1,%2,%3}, {%4,%5,%6,%7}, {%8,%9}, {%0,%1,%2,%3};"
        : "+f"(d[0]), "+f"(d[1]), "+f"(d[2]), "+f"(d[3])
        : "r"(a[0]), "r"(a[1]), "r"(a[2]), "r"(a[3]), "r"(b[0]), "r"(b[1]));
}

// ================= elementwise kernels =================
__global__ void convert_x_kernel(const float* __restrict__ X, u16* __restrict__ H,
                                 u16* __restrict__ L, int n4) {
    int i = blockIdx.x * blockDim.x + threadIdx.x;
    if (i >= n4) return;
    float4 v = ((const float4*)X)[i];
    uint32_t h01, h23, l01, l23;
    split4h(v, h01, h23, l01, l23);
    ((uint2*)H)[i] = make_uint2(h01, h23);
    ((uint2*)L)[i] = make_uint2(l01, l23);
}

__global__ void phi_norm_kernel(const float* __restrict__ phi,
                                u16* __restrict__ H, u16* __restrict__ L) {
    int i = blockIdx.x * blockDim.x + threadIdx.x;
    if (i >= DP * DD) return;
    float s = 0.f;
#pragma unroll 4
    for (int n = 0; n < DN; n++) { float v = phi[n * (DP * DD) + i]; s += v * v; }
    float r = rsqrtf(s + 1e-6f);
#pragma unroll 4
    for (int n = 0; n < DN; n++) {
        float v = phi[n * (DP * DD) + i] * r;
        split1h(v, H[n * (DP * DD) + i], L[n * (DP * DD) + i]);
    }
}

__global__ void softmax_row_kernel(const float* __restrict__ Lg,
                                   u16* __restrict__ H, u16* __restrict__ Lo) {
    const float* Lr = Lg + (size_t)blockIdx.x * DS;
    u16* Hr = H + (size_t)blockIdx.x * DS;
    u16* Or = Lo + (size_t)blockIdx.x * DS;
    int t = threadIdx.x;
    float v[4]; float mx = -1e30f;
#pragma unroll
    for (int j = 0; j < 4; j++) { v[j] = Lr[t + j * 256]; mx = fmaxf(mx, v[j]); }
    __shared__ float sd[256];
    sd[t] = mx; __syncthreads();
    for (int off = 128; off > 0; off >>= 1) { if (t < off) sd[t] = fmaxf(sd[t], sd[t + off]); __syncthreads(); }
    mx = sd[0]; __syncthreads();
    float sum = 0.f;
#pragma unroll
    for (int j = 0; j < 4; j++) { v[j] = expf(v[j] - mx); sum += v[j]; }
    sd[t] = sum; __syncthreads();
    for (int off = 128; off > 0; off >>= 1) { if (t < off) sd[t] += sd[t + off]; __syncthreads(); }
    float inv = 1.f / sd[0];
#pragma unroll
    for (int j = 0; j < 4; j++) {
        u16 hh, ll;
        split1h(v[j] * inv, hh, ll);
        Hr[t + j * 256] = hh; Or[t + j * 256] = ll;
    }
}

// 512 threads: (32, 16)
__global__ void softmax_col_kernel(const float* __restrict__ Lg,
                                   u16* __restrict__ H, u16* __restrict__ Lo) {
    int b = blockIdx.y;
    int s = blockIdx.x * 32 + threadIdx.x;
    int ty = threadIdx.y;
    const float* Lb = Lg + (size_t)b * DM * DS;
    u16* Hb = H + (size_t)b * DM * DS;
    u16* Ob = Lo + (size_t)b * DM * DS;
    __shared__ float red[16][32];
    float mx = -1e30f;
    for (int m = ty; m < DM; m += 16) mx = fmaxf(mx, Lb[(size_t)m * DS + s]);
    red[ty][threadIdx.x] = mx; __syncthreads();
    if (ty == 0) {
        float v = red[0][threadIdx.x];
#pragma unroll
        for (int i = 1; i < 16; i++) v = fmaxf(v, red[i][threadIdx.x]);
        red[0][threadIdx.x] = v;
    }
    __syncthreads();
    mx = red[0][threadIdx.x]; __syncthreads();
    float sum = 0.f;
    for (int m = ty; m < DM; m += 16) sum += expf(Lb[(size_t)m * DS + s] - mx);
    red[ty][threadIdx.x] = sum; __syncthreads();
    if (ty == 0) {
        float v = 0.f;
#pragma unroll
        for (int i = 0; i < 16; i++) v += red[i][threadIdx.x];
        red[0][threadIdx.x] = v;
    }
    __syncthreads();
    float inv = 1.f / red[0][threadIdx.x];
    for (int m = ty; m < DM; m += 16) {
        u16 hh, ll;
        split1h(expf(Lb[(size_t)m * DS + s] - mx) * inv, hh, ll);
        Hb[(size_t)m * DS + s] = hh; Ob[(size_t)m * DS + s] = ll;
    }
}

// LayerNorm: read Xs [b][n*16+p][d], write LN planes [n][b*16+p][d]
__global__ void layernorm_kernel(const float* __restrict__ X,
                                 u16* __restrict__ H, u16* __restrict__ L,
                                 const float* __restrict__ g, const float* __restrict__ bb) {
    int row = blockIdx.x;
    int b = row >> 10;
    int slot = row & 1023;
    int n = slot >> 4;
    int p = slot & 15;
    const float* Xr = X + (size_t)row * DD;
    size_t obase = ((size_t)n * 128 + b * 16 + p) * DD;
    __shared__ float sh[DD];
    __shared__ float red[256];
    int t = threadIdx.x;
    float ls = 0.f;
    for (int j = t; j < DD; j += 256) { float v = Xr[j]; sh[j] = v; ls += v; }
    red[t] = ls; __syncthreads();
    for (int off = 128; off > 0; off >>= 1) { if (t < off) red[t] += red[t + off]; __syncthreads(); }
    float mu = red[0] * (1.0f / DD); __syncthreads();
    float lv = 0.f;
    for (int j = t; j < DD; j += 256) { float dv = sh[j] - mu; lv += dv * dv; }
    red[t] = lv; __syncthreads();
    for (int off = 128; off > 0; off >>= 1) { if (t < off) red[t] += red[t + off]; __syncthreads(); }
    float is = rsqrtf(red[0] * (1.0f / DD) + 1e-5f); __syncthreads();
    for (int j = t; j < DD; j += 256) {
        float v = (sh[j] - mu) * is * g[n * DD + j] + bb[n * DD + j];
        u16 hh, ll;
        split1h(v, hh, ll);
        H[obase + j] = hh; L[obase + j] = ll;
    }
}

// ================= cp.async mma GEMM =================
// 256 threads, 8 warps 4(M)x2(N); warp tile 32x32; CTA tile 128x64, kc=32.
// A from fp16 planes (hi+lo) via cp.async. B: BPRE=1 planes via cp.async
// (BPL=1 hi only -> 2-term; BPL=2 hi+lo -> 3-term); BPRE=0 fp32 weights via
// LDG+cvt+STS (single-rounded hi, 2-term).
// TA/TB: 0 = row-major [row][K], 1 = K-major [K][row]
// EPI: 0 none, 1 +bias, 2 +bias+gelu ; CSC: scattered rows
// OSPLIT: 0 fp32 out, 1 one fp16 plane, 2 two fp16 planes
template <int TA, int TB, int BPRE, int BPL, int EPI, int CSC, int OSPLIT, int MINB>
__global__ void __launch_bounds__(256, MINB)
gemm_ca(const u16* __restrict__ Ah, const u16* __restrict__ Al,
        const u16* __restrict__ Bh, const u16* __restrict__ Bl,
        const float* __restrict__ Bf,
        float* __restrict__ Cf, u16* __restrict__ Ph, u16* __restrict__ Pl,
        const float* __restrict__ bias,
        int K, int lda, int ldb, int ldc,
        long long aBS, long long bBS, long long cBS, int biasBS, long long c_sb) {
    constexpr int ASZ1 = TA ? 32 * 272 : 128 * 80;
    constexpr int BSZ1 = TB ? 32 * 144 : 64 * 80;
    constexpr int STAGE = 2 * ASZ1 + BPL * BSZ1;
    extern __shared__ char smem[];
    const uint32_t sm0 = smem_to_u32(smem);

    const int tid = threadIdx.x;
    const int l = tid & 31;
    const int wid = tid >> 5;
    const int wm = wid & 3;
    const int wn = wid >> 2;
    const int z = blockIdx.z;
    const int bm = blockIdx.y * 128;
    const int bn = blockIdx.x * 64;
    const int NC = K >> 5;

    const u16* Ahb = Ah + z * aBS + (TA ? (size_t)bm : (size_t)bm * lda);
    const u16* Alb = Al + z * aBS + (TA ? (size_t)bm : (size_t)bm * lda);
    const u16* Bhb = BPRE ? (Bh + z * bBS + (TB ? (size_t)bn : (size_t)bn * ldb)) : nullptr;
    const u16* Blb = (BPRE && BPL == 2) ? (Bl + z * bBS + (TB ? (size_t)bn : (size_t)bn * ldb)) : nullptr;
    const float* Bfb = BPRE ? nullptr : (Bf + z * bBS + (size_t)bn);   // weights always TB=1, col offset

    float4 rbf[2];   // weights LDG buffer (BPRE=0 only)

    auto CPA = [&](int c, int s) {
        uint32_t sb = sm0 + s * STAGE;
        int k0 = c * 32;
#pragma unroll
        for (int i = 0; i < 2; i++) {
            int idx = tid + i * 256;
            if (TA == 0) {
                int row = idx >> 2, o = idx & 3;
                size_t go = (size_t)row * lda + k0 + o * 8;
                CP16(sb + row * 80 + o * 16, Ahb + go);
                CP16(sb + ASZ1 + row * 80 + o * 16, Alb + go);
            } else {
                int row = idx >> 4, o = idx & 15;
                size_t go = (size_t)(k0 + row) * lda + o * 8;
                CP16(sb + row * 272 + o * 16, Ahb + go);
                CP16(sb + ASZ1 + row * 272 + o * 16, Alb + go);
            }
        }
    };

    auto CPB = [&](int c, int s) {
        uint32_t sb = sm0 + s * STAGE + 2 * ASZ1;
        int k0 = c * 32;
        if (TB == 0) {
            int row = tid >> 2, o = tid & 3;
            size_t go = (size_t)row * ldb + k0 + o * 8;
            CP16(sb + row * 80 + o * 16, Bhb + go);
            if (BPL == 2) CP16(sb + BSZ1 + row * 80 + o * 16, Blb + go);
        } else {
            int row = tid >> 3, o = tid & 7;
            size_t go = (size_t)(k0 + row) * ldb + o * 8;
            CP16(sb + row * 144 + o * 16, Bhb + go);
            if (BPL == 2) CP16(sb + BSZ1 + row * 144 + o * 16, Blb + go);
        }
    };

    auto LDGW = [&](int c) {   // weights fp32, TB=1
        int k0 = c * 32;
#pragma unroll
        for (int i = 0; i < 2; i++) {
            int p = tid + i * 256;
            rbf[i] = *(const float4*)(Bfb + (size_t)(k0 + (p >> 4)) * ldb + (p & 15) * 4);
        }
    };
    auto STSW = [&](int s) {
        char* bh = smem + s * STAGE + 2 * ASZ1;
#pragma unroll
        for (int i = 0; i < 2; i++) {
            int p = tid + i * 256;
            uint32_t h01, h23;
            hi4h(rbf[i], h01, h23);
            *(uint2*)(bh + (p >> 4) * 144 + (p & 15) * 8) = make_uint2(h01, h23);
        }
    };

    float acc[2][4][4];
#pragma unroll
    for (int mt = 0; mt < 2; mt++)
#pragma unroll
        for (int nt = 0; nt < 4; nt++)
#pragma unroll
            for (int q = 0; q < 4; q++) acc[mt][nt][q] = 0.f;

    auto COMPUTE = [&](int s) {
        uint32_t sbA = sm0 + s * STAGE;
        uint32_t sbB = sbA + 2 * ASZ1;
#pragma unroll
        for (int ks = 0; ks < 2; ks++) {
            uint32_t ahi[2][4], alo[2][4];
#pragma unroll
            for (int mt = 0; mt < 2; mt++) {
                int mr = wm * 32 + mt * 16;
                if (TA) {
                    int krow = ks * 16 + (l & 7) + ((l >> 4) << 3);
                    int col = mr + (((l >> 3) & 1) << 3);
                    uint32_t addr = sbA + krow * 272 + col * 2;
                    ldsm_x4_t(ahi[mt], addr);
                    ldsm_x4_t(alo[mt], addr + ASZ1);
                } else {
                    int row = mr + (l & 15);
                    uint32_t addr = sbA + row * 80 + ks * 32 + ((l >> 4) & 1) * 16;
                    ldsm_x4(ahi[mt], addr);
                    ldsm_x4(alo[mt], addr + ASZ1);
                }
            }
#pragma unroll
            for (int np = 0; np < 2; np++) {
                int nr = wn * 32 + np * 16;
                uint32_t bhi[4], blo[4];
                if (TB) {
                    int krow = ks * 16 + (l & 7) + (((l >> 3) & 1) << 3);
                    int col = nr + ((l >> 4) << 3);
                    uint32_t addr = sbB + krow * 144 + col * 2;
                    ldsm_x4_t(bhi, addr);
                    if (BPL == 2) ldsm_x4_t(blo, addr + BSZ1);
                } else {
                    int row = nr + (l & 7) + ((l >> 4) << 3);
                    uint32_t addr = sbB + row * 80 + ks * 32 + (((l >> 3) & 1) << 4);
                    ldsm_x4(bhi, addr);
                    if (BPL == 2) ldsm_x4(blo, addr + BSZ1);
                }
#pragma unroll
                for (int half = 0; half < 2; half++) {
                    int nt = np * 2 + half;
#pragma unroll
                    for (int mt = 0; mt < 2; mt++) {
                        mma_f16(acc[mt][nt], ahi[mt], bhi + 2 * half);
                        mma_f16(acc[mt][nt], alo[mt], bhi + 2 * half);
                        if (BPL == 2) mma_f16(acc[mt][nt], ahi[mt], blo + 2 * half);
                    }
                }
            }
        }
    };

    // prologue
    CPA(0, 0);
    if (BPRE) CPB(0, 0); else { LDGW(0); STSW(0); }
    CP_COMMIT();
    if (NC > 1) {
        CPA(1, 1);
        if (BPRE) CPB(1, 1); else { LDGW(1); STSW(1); }
    }
    CP_COMMIT();

    for (int c = 0; c < NC; c++) {
        int s = c & 1;
        CP_WAIT1();
        __syncthreads();
        if (!BPRE && c + 2 < NC) LDGW(c + 2);
        COMPUTE(s);
        __syncthreads();
        if (c + 2 < NC) {
            CPA(c + 2, s);
            if (BPRE) CPB(c + 2, s); else STSW(s);
        }
        CP_COMMIT();
    }

    // ---------------- epilogue via smem staging ----------------
    float* Cs = (float*)smem;   // [128][68]
#pragma unroll
    for (int mt = 0; mt < 2; mt++) {
#pragma unroll
        for (int nt = 0; nt < 4; nt++) {
            int r0 = wm * 32 + mt * 16 + (l >> 2);
            int c0 = wn * 32 + nt * 8 + (l & 3) * 2;
            Cs[r0 * 68 + c0] = acc[mt][nt][0];
            Cs[r0 * 68 + c0 + 1] = acc[mt][nt][1];
            Cs[(r0 + 8) * 68 + c0] = acc[mt][nt][2];
            Cs[(r0 + 8) * 68 + c0 + 1] = acc[mt][nt][3];
        }
    }
    __syncthreads();
    const float* bp = (EPI >= 1) ? (bias + (size_t)z * biasBS + bn) : nullptr;
#pragma unroll 4
    for (int i = 0; i < 32; i++) {
        int idx = i * 256 + tid;
        int r = idx >> 6, cc = idx & 63;
        float v = Cs[r * 68 + cc];
        if (EPI >= 1) v += __ldg(bp + cc);
        if (EPI == 2) v = 0.5f * v * (1.0f + erff(v * 0.70710678118654752440f));
        size_t off;
        if (CSC)
            off = (size_t)z * cBS + (size_t)(r >> 4) * c_sb + (size_t)(r & 15) * ldc + bn + cc;
        else
            off = (size_t)z * cBS + (size_t)(bm + r) * ldc + bn + cc;
        if (OSPLIT == 0) {
            Cf[off] = v;
        } else if (OSPLIT == 1) {
            u16 hu;
            asm("cvt.rn.f16.f32 %0, %1;" : "=h"(hu) : "f"(v));
            Ph[off] = hu;
        } else {
            u16 hu, lu;
            split1h(v, hu, lu);
            Ph[off] = hu; Pl[off] = lu;
        }
    }
}

// ================= host launcher =================
extern "C" void kernel_launch(void* const* d_in, const int* in_sizes, int n_in,
                              void* d_out, int out_size) {
    const float* x    = (const float*)d_in[0];
    const float* phi  = (const float*)d_in[1];
    const float* ln_g = (const float*)d_in[2];
    const float* ln_b = (const float*)d_in[3];
    const float* w1   = (const float*)d_in[4];
    const float* b1   = (const float*)d_in[5];
    const float* w2   = (const float*)d_in[6];
    const float* b2   = (const float*)d_in[7];
    float* out = (float*)d_out;

    float *logits, *Xs;
    u16 *xh, *xl, *ph, *pl, *Ch, *Cl, *Dh, *Dl, *LNh, *LNl, *hh, *hl, *Yh;
    cudaGetSymbolAddress((void**)&logits, g_logits);
    cudaGetSymbolAddress((void**)&Xs, g_Xs);
    cudaGetSymbolAddress((void**)&xh, g_xh);   cudaGetSymbolAddress((void**)&xl, g_xl);
    cudaGetSymbolAddress((void**)&ph, g_ph);   cudaGetSymbolAddress((void**)&pl, g_pl);
    cudaGetSymbolAddress((void**)&Ch, g_Ch);   cudaGetSymbolAddress((void**)&Cl, g_Cl);
    cudaGetSymbolAddress((void**)&Dh, g_Dh);   cudaGetSymbolAddress((void**)&Dl, g_Dl);
    cudaGetSymbolAddress((void**)&LNh, g_LNh); cudaGetSymbolAddress((void**)&LNl, g_LNl);
    cudaGetSymbolAddress((void**)&hh, g_hh);   cudaGetSymbolAddress((void**)&hl, g_hl);
    cudaGetSymbolAddress((void**)&Yh, g_Yh);

    const int EPI_BYTES = 128 * 68 * 4;
    auto mx = [](int a, int b) { return a > b ? a : b; };
    const int SM_G2  = mx(2 * (2 * 128 * 80 + 2 * 64 * 80), EPI_BYTES);   // 61440
    const int SM_G4  = mx(2 * (2 * 32 * 272 + 32 * 144), EPI_BYTES);      // 44032
    const int SM_G67 = mx(2 * (2 * 128 * 80 + 32 * 144), EPI_BYTES);      // 50176
    cudaFuncSetAttribute(gemm_ca<0,0,1,2,0,0,0,2>, cudaFuncAttributeMaxDynamicSharedMemorySize, SM_G2);
    cudaFuncSetAttribute(gemm_ca<1,1,1,1,0,0,0,3>, cudaFuncAttributeMaxDynamicSharedMemorySize, SM_G4);
    cudaFuncSetAttribute(gemm_ca<0,1,0,1,2,0,2,3>, cudaFuncAttributeMaxDynamicSharedMemorySize, SM_G67);
    cudaFuncSetAttribute(gemm_ca<0,1,0,1,1,1,1,3>, cudaFuncAttributeMaxDynamicSharedMemorySize, SM_G67);
    cudaFuncSetAttribute(gemm_ca<0,1,1,1,0,0,0,3>, cudaFuncAttributeMaxDynamicSharedMemorySize, SM_G67);

    // 0. split x into fp16 planes
    convert_x_kernel<<<(DB * DM * DD / 4 + 255) / 256, 256>>>(x, xh, xl, DB * DM * DD / 4);

    // 1. normalize + split phi
    phi_norm_kernel<<<(DP * DD + 255) / 256, 256>>>(phi, ph, pl);

    // 2. logits = x @ phin^T   (3-term: A planes, B planes hi+lo)
    gemm_ca<0,0,1,2,0,0,0,2><<<dim3(DS / 64, (DB * DM) / 128, 1), 256, SM_G2>>>(
        xh, xl, ph, pl, nullptr, logits, nullptr, nullptr, nullptr,
        DD, DD, DD, DS, 0, 0, 0, 0, 0);

    // 3a. dispatch softmax (D planes)
    softmax_col_kernel<<<dim3(DS / 32, DB), dim3(32, 16)>>>(logits, Dh, Dl);

    // 4. Xs = D^T @ x   (A = D planes K-major, B = xh K-major, 2-term)
    gemm_ca<1,1,1,1,0,0,0,3><<<dim3(DD / 64, DS / 128, DB), 256, SM_G4>>>(
        Dh, Dl, xh, nullptr, nullptr, Xs, nullptr, nullptr, nullptr,
        DM, DS, DD, DD,
        (long long)DM * DS, (long long)DM * DD, (long long)DS * DD, 0, 0);

    // 3b. combine softmax (C planes)
    softmax_row_kernel<<<DB * DM, 256>>>(logits, Ch, Cl);

    // 5. LayerNorm -> LN planes (expert layout)
    layernorm_kernel<<<DB * DS, 256>>>(Xs, LNh, LNl, ln_g, ln_b);

    // 6. hdn = LN @ w1 + b1, GELU -> hdn planes  (B = w1 fp32 K-major)
    gemm_ca<0,1,0,1,2,0,2,3><<<dim3(DH / 64, 1, DN), 256, SM_G67>>>(
        LNh, LNl, nullptr, nullptr, w1, nullptr, hh, hl, b1,
        DD, DD, DH, DH,
        (long long)128 * DD, (long long)DD * DH, (long long)128 * DH, DH, 0);

    // 7. Ys = hdn @ w2 + b2 -> Yh (single plane), scattered
    gemm_ca<0,1,0,1,1,1,1,3><<<dim3(DD / 64, 1, DN), 256, SM_G67>>>(
        hh, hl, nullptr, nullptr, w2, nullptr, Yh, nullptr, b2,
        DH, DH, DD, DD,
        (long long)128 * DH, (long long)DH * DD, (long long)DP * DD, DD,
        (long long)DS * DD);

    // 8. Y = C @ Ys   (A = C planes, B = Yh K-major, 2-term)
    gemm_ca<0,1,1,1,0,0,0,3><<<dim3(DD / 64, DM / 128, DB), 256, SM_G67>>>(
        Ch, Cl, Yh, nullptr, nullptr, out, nullptr, nullptr, nullptr,
        DS, DS, DD, DD,
        (long long)DM * DS, (long long)DS * DD, (long long)DM * DD, 0, 0);
}